// round 6
// baseline (speedup 1.0000x reference)
#include <cuda_runtime.h>
#include <cstdint>
#include <cstddef>

// CTRNN persistent kernel, round 6: one CTA barrier per step.
// T=512, B=256, I=64, H=256. 128 CTAs x 512 threads, 2 batches/CTA.
//
// 4 k-groups of 128 threads; group g owns augmented rows [80g, 80g+80)
// (aug = 64 x-rows followed by 256 h-rows) in a PRIVATE smem slice, and
// serves outputs j0 = tid&127, j1 = j0+128 (one h-broadcast feeds both).
// Per group: 48 W rows via smem ([chunk][j] 16B slots), 32 register-resident.
//
// Step structure:
//   FMA phase (reads own slice) -> write 4 partials to parity red buffer
//   __syncthreads()                     (single full-CTA barrier)
//   finalize: each group reads all partials for ITS OWN disjoint j-range
//     (g0: j 0..15 + x[t+1] staging; g1: 16..95; g2: 96..175; g3: 176..255),
//     computes h[t+1], writes out + own slice
//   bar.sync g+1, 128                   (4-warp group barrier)
// red is double-buffered by t parity (cross-step race freedom proved via the
// CTA barrier of the intervening step). haug slices are group-private.

#define T_STEPS 512
#define BATCH   256
#define IN_SZ   64
#define HID     256
#define NTHR    512
#define NCTA    (BATCH / 2)

#define NGROUP        4
#define ROWS_PER_G    80
#define CHUNKS_PER_G  12          // 48 smem W rows per group
#define SMEM_ROWS_G   48
#define RF_U64        16          // 32 reg W rows per group (per j)
#define TOTAL_CHUNKS  (NGROUP * CHUNKS_PER_G)   // 48

typedef unsigned long long u64;

#define SMEM_W_BYTES   (TOTAL_CHUNKS * HID * 16)     // 196608
#define HAUG_STRIDE    96                            // 80 rows + pad (16B mult)
#define HAUG_OFF       SMEM_W_BYTES
#define RED_OFF        (HAUG_OFF + NGROUP * 2 * HAUG_STRIDE * 4)   // +3072
#define RED_PAR_FLOATS (2 * NGROUP * HID)            // 2048 per parity
#define SMEM_TOTAL     (RED_OFF + 2 * RED_PAR_FLOATS * 4)          // 216064

__device__ __forceinline__ u64 fma2(u64 a, u64 b, u64 c) {
    u64 d;
    asm("fma.rn.f32x2 %0, %1, %2, %3;" : "=l"(d) : "l"(a), "l"(b), "l"(c));
    return d;
}
__device__ __forceinline__ u64 add2(u64 a, u64 b) {
    u64 d;
    asm("add.rn.f32x2 %0, %1, %2;" : "=l"(d) : "l"(a), "l"(b));
    return d;
}
__device__ __forceinline__ float sum2(u64 a) {
    float lo, hi;
    asm("mov.b64 {%0, %1}, %2;" : "=f"(lo), "=f"(hi) : "l"(a));
    return lo + hi;
}
__device__ __forceinline__ const float* wrow(const float* Win, const float* Whh,
                                             int j, int aug) {
    return (aug < IN_SZ) ? &Win[j * IN_SZ + aug] : &Whh[j * HID + (aug - IN_SZ)];
}

__global__ void __launch_bounds__(NTHR, 1)
ctrnn_1bar_kernel(const float* __restrict__ x,
                  const float* __restrict__ h0,
                  const float* __restrict__ noise,
                  const float* __restrict__ Win,
                  const float* __restrict__ bin,
                  const float* __restrict__ Whh,
                  const float* __restrict__ bhh,
                  float* __restrict__ out,
                  float* __restrict__ hlast)
{
    extern __shared__ unsigned char smem_raw[];
    ulonglong2* Wsm = reinterpret_cast<ulonglong2*>(smem_raw);
    float* haug = reinterpret_cast<float*>(smem_raw + HAUG_OFF);  // [4][2][96]
    float* red  = reinterpret_cast<float*>(smem_raw + RED_OFF);   // [2][2][4][256]

    const int tid = threadIdx.x;
    const int g   = tid >> 7;          // k-group 0..3
    const int jl  = tid & 127;
    const int j0  = jl;
    const int j1  = jl + 128;
    const int b0  = blockIdx.x * 2;
    const int b1  = b0 + 1;

    // ---- stage W smem: chunk i covers aug rows 80g+4i..+3, cols j0 and j1 ----
    for (int i = 0; i < CHUNKS_PER_G; ++i) {
        const int aug = ROWS_PER_G * g + 4 * i;
        *reinterpret_cast<float4*>(&Wsm[(g * CHUNKS_PER_G + i) * HID + j0]) =
            *reinterpret_cast<const float4*>(wrow(Win, Whh, j0, aug));
        *reinterpret_cast<float4*>(&Wsm[(g * CHUNKS_PER_G + i) * HID + j1]) =
            *reinterpret_cast<const float4*>(wrow(Win, Whh, j1, aug));
    }

    // ---- register W rows: aug 80g+48 .. 80g+79 ----
    u64 wr0[RF_U64], wr1[RF_U64];
    #pragma unroll
    for (int m = 0; m < RF_U64; ++m) {
        const int aug = ROWS_PER_G * g + SMEM_ROWS_G + 2 * m;
        wr0[m] = *reinterpret_cast<const u64*>(wrow(Win, Whh, j0, aug));
        wr1[m] = *reinterpret_cast<const u64*>(wrow(Win, Whh, j1, aug));
    }

    // ---- finalize identity for this thread ----
    const int  nrows = (g == 0) ? 16 : 80;
    const bool act   = jl < nrows;
    const int  myj   = (g == 0) ? jl : ((g == 1 ? 16 : (g == 2 ? 96 : 176)) + jl);
    const int  lidx  = (g == 0) ? 64 + jl : jl;   // index within own slice
    const float bsum = act ? (bin[myj] + bhh[myj]) : 0.f;

    // x staging identity (group 0 only): thread jl -> (batch sel, x index)
    const int xb = jl >> 6;            // 0 -> batch A, 1 -> batch B
    const int xi = jl & 63;
    const int xbatch = xb ? b1 : b0;

    float* myA = haug + (g * 2 + 0) * HAUG_STRIDE;   // own slice, batch A
    float* myB = haug + (g * 2 + 1) * HAUG_STRIDE;   // own slice, batch B

    // ---- initial staging of own slice: h0 part + x(t=0) part ----
    if (act) {
        myA[lidx] = h0[b0 * HID + myj];
        myB[lidx] = h0[b1 * HID + myj];
    }
    if (g == 0)
        (xb ? myB : myA)[xi] = x[(size_t)xbatch * IN_SZ + xi];
    float nz = act ? (noise[myj] + bsum) : 0.f;
    __syncthreads();

    const ulonglong2* wp0 = Wsm + (size_t)(g * CHUNKS_PER_G) * HID + j0;
    const ulonglong2* wp1 = Wsm + (size_t)(g * CHUNKS_PER_G) * HID + j1;

    for (int t = 0; t < T_STEPS; ++t) {
        float* redp = red + (t & 1) * RED_PAR_FLOATS;

        // prefetch next x / noise (latency hidden under FMA phase)
        const int tn = (t + 1 < T_STEPS) ? t + 1 : t;
        float xn = 0.f, nzn = 0.f;
        if (g == 0) xn = x[((size_t)tn * BATCH + xbatch) * IN_SZ + xi];
        if (act)    nzn = noise[(size_t)tn * HID + myj] + bsum;

        // ---- FMA phase over own slice (rows 0..79 local) ----
        u64 aA00 = 0, aA01 = 0, aA10 = 0, aA11 = 0;
        u64 aB00 = 0, aB01 = 0, aB10 = 0, aB11 = 0;

        #pragma unroll
        for (int c = 0; c < CHUNKS_PER_G; ++c) {
            ulonglong2 w0 = wp0[(size_t)c * HID];
            ulonglong2 w1 = wp1[(size_t)c * HID];
            ulonglong2 ha = *reinterpret_cast<const ulonglong2*>(&myA[4 * c]);
            ulonglong2 hb = *reinterpret_cast<const ulonglong2*>(&myB[4 * c]);
            aA00 = fma2(w0.x, ha.x, aA00);  aA01 = fma2(w0.y, ha.y, aA01);
            aA10 = fma2(w1.x, ha.x, aA10);  aA11 = fma2(w1.y, ha.y, aA11);
            aB00 = fma2(w0.x, hb.x, aB00);  aB01 = fma2(w0.y, hb.y, aB01);
            aB10 = fma2(w1.x, hb.x, aB10);  aB11 = fma2(w1.y, hb.y, aB11);
        }
        #pragma unroll
        for (int i = 0; i < RF_U64 / 2; ++i) {
            ulonglong2 ha = *reinterpret_cast<const ulonglong2*>(&myA[SMEM_ROWS_G + 4 * i]);
            ulonglong2 hb = *reinterpret_cast<const ulonglong2*>(&myB[SMEM_ROWS_G + 4 * i]);
            aA00 = fma2(wr0[2 * i], ha.x, aA00);  aA01 = fma2(wr0[2 * i + 1], ha.y, aA01);
            aA10 = fma2(wr1[2 * i], ha.x, aA10);  aA11 = fma2(wr1[2 * i + 1], ha.y, aA11);
            aB00 = fma2(wr0[2 * i], hb.x, aB00);  aB01 = fma2(wr0[2 * i + 1], hb.y, aB01);
            aB10 = fma2(wr1[2 * i], hb.x, aB10);  aB11 = fma2(wr1[2 * i + 1], hb.y, aB11);
        }

        redp[(0 * NGROUP + g) * HID + j0] = sum2(add2(aA00, aA01));
        redp[(0 * NGROUP + g) * HID + j1] = sum2(add2(aA10, aA11));
        redp[(1 * NGROUP + g) * HID + j0] = sum2(add2(aB00, aB01));
        redp[(1 * NGROUP + g) * HID + j1] = sum2(add2(aB10, aB11));
        __syncthreads();                       // the ONE full-CTA barrier

        // ---- finalize own j-range ----
        if (act) {
            const float* rA = redp;
            const float* rB = redp + NGROUP * HID;
            const float sA = rA[0 * HID + myj] + rA[1 * HID + myj]
                           + rA[2 * HID + myj] + rA[3 * HID + myj];
            const float sB = rB[0 * HID + myj] + rB[1 * HID + myj]
                           + rB[2 * HID + myj] + rB[3 * HID + myj];
            const float hnA = fmaxf(myA[lidx] * 0.8f + (sA + nz) * 0.2f, 0.f);
            const float hnB = fmaxf(myB[lidx] * 0.8f + (sB + nz) * 0.2f, 0.f);
            if (out) {
                out[((size_t)t * BATCH + b0) * HID + myj] = hnA;
                out[((size_t)t * BATCH + b1) * HID + myj] = hnB;
            }
            myA[lidx] = hnA;
            myB[lidx] = hnB;
        }
        if (g == 0)
            (xb ? myB : myA)[xi] = xn;         // stage x[t+1] into own slice
        nz = nzn;

        asm volatile("bar.sync %0, %1;" :: "r"(g + 1), "r"(128) : "memory");
    }

    if (hlast && act) {
        hlast[b0 * HID + myj] = myA[lidx];
        hlast[b1 * HID + myj] = myB[lidx];
    }
}

extern "C" void kernel_launch(void* const* d_in, const int* in_sizes, int n_in,
                              void* d_out, int out_size)
{
    const float* x     = (const float*)d_in[0];   // [512,256,64]
    const float* h0    = (const float*)d_in[1];   // [256,256]
    const float* noise = (const float*)d_in[2];   // [512,256]
    const float* Win   = (const float*)d_in[3];   // [256,64]
    const float* bin   = (const float*)d_in[4];   // [256]
    const float* Whh   = (const float*)d_in[5];   // [256,256]
    const float* bhh   = (const float*)d_in[6];   // [256]

    const size_t TBH = (size_t)T_STEPS * BATCH * HID;
    const size_t BH  = (size_t)BATCH * HID;

    float* out   = nullptr;
    float* hlast = nullptr;
    if ((size_t)out_size >= TBH) {
        out = (float*)d_out;
        if ((size_t)out_size >= TBH + BH) hlast = (float*)d_out + TBH;
    } else {
        hlast = (float*)d_out;
    }

    static bool attr_set = false;
    if (!attr_set) {
        cudaFuncSetAttribute(ctrnn_1bar_kernel,
                             cudaFuncAttributeMaxDynamicSharedMemorySize, SMEM_TOTAL);
        attr_set = true;
    }

    ctrnn_1bar_kernel<<<NCTA, NTHR, SMEM_TOTAL>>>(
        x, h0, noise, Win, bin, Whh, bhh, out, hlast);
}

// round 7
// speedup vs baseline: 1.0567x; 1.0567x over previous
#include <cuda_runtime.h>
#include <cstdint>
#include <cstddef>

// CTRNN persistent kernel, round 7: R6 chassis + W-load software pipelining.
// T=512, B=256, I=64, H=256. 128 CTAs x 512 threads, 2 batches/CTA.
//
// 4 k-groups of 128 threads; group g owns augmented rows [80g, 80g+80)
// in a PRIVATE smem slice; serves outputs j0 = tid&127, j1 = j0+128.
// Per group: 48 W rows via smem, 32 register-resident.
//
// New in R7:
//  * 1-chunk W register lookahead with wraparound: chunk c consumes the
//    buffer while the LDS for chunk (c+1)%12 issues; the c=11 load fetches
//    NEXT step's chunk 0 BEFORE the CTA barrier (W smem is constant after
//    init, so hoisting across the barrier is safe). Keeps the L1/LDS return
//    path busy across the red-exchange/finalize/barrier gap that previously
//    idled it ~28% of each step.
//  * Accumulators merged 8 -> 4 u64 (one chain per batch x j) to pay for
//    the lookahead registers; 4-way ILP per thread keeps FMA pipe fed.

#define T_STEPS 512
#define BATCH   256
#define IN_SZ   64
#define HID     256
#define NTHR    512
#define NCTA    (BATCH / 2)

#define NGROUP        4
#define ROWS_PER_G    80
#define CHUNKS_PER_G  12          // 48 smem W rows per group
#define SMEM_ROWS_G   48
#define RF_U64        16          // 32 reg W rows per group (per j)
#define TOTAL_CHUNKS  (NGROUP * CHUNKS_PER_G)   // 48

typedef unsigned long long u64;

#define SMEM_W_BYTES   (TOTAL_CHUNKS * HID * 16)     // 196608
#define HAUG_STRIDE    96                            // 80 rows + pad (16B mult)
#define HAUG_OFF       SMEM_W_BYTES
#define RED_OFF        (HAUG_OFF + NGROUP * 2 * HAUG_STRIDE * 4)   // +3072
#define RED_PAR_FLOATS (2 * NGROUP * HID)            // 2048 per parity
#define SMEM_TOTAL     (RED_OFF + 2 * RED_PAR_FLOATS * 4)          // 216064

__device__ __forceinline__ u64 fma2(u64 a, u64 b, u64 c) {
    u64 d;
    asm("fma.rn.f32x2 %0, %1, %2, %3;" : "=l"(d) : "l"(a), "l"(b), "l"(c));
    return d;
}
__device__ __forceinline__ float sum2(u64 a) {
    float lo, hi;
    asm("mov.b64 {%0, %1}, %2;" : "=f"(lo), "=f"(hi) : "l"(a));
    return lo + hi;
}
__device__ __forceinline__ const float* wrow(const float* Win, const float* Whh,
                                             int j, int aug) {
    return (aug < IN_SZ) ? &Win[j * IN_SZ + aug] : &Whh[j * HID + (aug - IN_SZ)];
}

__global__ void __launch_bounds__(NTHR, 1)
ctrnn_wpipe_kernel(const float* __restrict__ x,
                   const float* __restrict__ h0,
                   const float* __restrict__ noise,
                   const float* __restrict__ Win,
                   const float* __restrict__ bin,
                   const float* __restrict__ Whh,
                   const float* __restrict__ bhh,
                   float* __restrict__ out,
                   float* __restrict__ hlast)
{
    extern __shared__ unsigned char smem_raw[];
    ulonglong2* Wsm = reinterpret_cast<ulonglong2*>(smem_raw);
    float* haug = reinterpret_cast<float*>(smem_raw + HAUG_OFF);  // [4][2][96]
    float* red  = reinterpret_cast<float*>(smem_raw + RED_OFF);   // [2][2][4][256]

    const int tid = threadIdx.x;
    const int g   = tid >> 7;          // k-group 0..3
    const int jl  = tid & 127;
    const int j0  = jl;
    const int j1  = jl + 128;
    const int b0  = blockIdx.x * 2;
    const int b1  = b0 + 1;

    // ---- stage W smem: chunk i covers aug rows 80g+4i..+3, cols j0 and j1 ----
    for (int i = 0; i < CHUNKS_PER_G; ++i) {
        const int aug = ROWS_PER_G * g + 4 * i;
        *reinterpret_cast<float4*>(&Wsm[(g * CHUNKS_PER_G + i) * HID + j0]) =
            *reinterpret_cast<const float4*>(wrow(Win, Whh, j0, aug));
        *reinterpret_cast<float4*>(&Wsm[(g * CHUNKS_PER_G + i) * HID + j1]) =
            *reinterpret_cast<const float4*>(wrow(Win, Whh, j1, aug));
    }

    // ---- register W rows: aug 80g+48 .. 80g+79 ----
    u64 wr0[RF_U64], wr1[RF_U64];
    #pragma unroll
    for (int m = 0; m < RF_U64; ++m) {
        const int aug = ROWS_PER_G * g + SMEM_ROWS_G + 2 * m;
        wr0[m] = *reinterpret_cast<const u64*>(wrow(Win, Whh, j0, aug));
        wr1[m] = *reinterpret_cast<const u64*>(wrow(Win, Whh, j1, aug));
    }

    // ---- finalize identity ----
    const int  nrows = (g == 0) ? 16 : 80;
    const bool act   = jl < nrows;
    const int  myj   = (g == 0) ? jl : ((g == 1 ? 16 : (g == 2 ? 96 : 176)) + jl);
    const int  lidx  = (g == 0) ? 64 + jl : jl;   // index within own slice
    const float bsum = act ? (bin[myj] + bhh[myj]) : 0.f;

    // x staging identity (group 0 only)
    const int xb = jl >> 6;
    const int xi = jl & 63;
    const int xbatch = xb ? b1 : b0;

    float* myA = haug + (g * 2 + 0) * HAUG_STRIDE;
    float* myB = haug + (g * 2 + 1) * HAUG_STRIDE;

    // ---- initial staging of own slice ----
    if (act) {
        myA[lidx] = h0[b0 * HID + myj];
        myB[lidx] = h0[b1 * HID + myj];
    }
    if (g == 0)
        (xb ? myB : myA)[xi] = x[(size_t)xbatch * IN_SZ + xi];
    float nz = act ? (noise[myj] + bsum) : 0.f;
    __syncthreads();

    const ulonglong2* wp0 = Wsm + (size_t)(g * CHUNKS_PER_G) * HID + j0;
    const ulonglong2* wp1 = Wsm + (size_t)(g * CHUNKS_PER_G) * HID + j1;

    // ---- prime the 1-chunk W lookahead (chunk 0) ----
    ulonglong2 wb0 = wp0[0];
    ulonglong2 wb1 = wp1[0];

    for (int t = 0; t < T_STEPS; ++t) {
        float* redp = red + (t & 1) * RED_PAR_FLOATS;

        // prefetch next x / noise
        const int tn = (t + 1 < T_STEPS) ? t + 1 : t;
        float xn = 0.f, nzn = 0.f;
        if (g == 0) xn = x[((size_t)tn * BATCH + xbatch) * IN_SZ + xi];
        if (act)    nzn = noise[(size_t)tn * HID + myj] + bsum;

        // ---- FMA phase: 4 accumulator chains (batch x j) ----
        u64 aA0 = 0, aA1 = 0, aB0 = 0, aB1 = 0;

        #pragma unroll
        for (int c = 0; c < CHUNKS_PER_G; ++c) {
            const ulonglong2 w0 = wb0;
            const ulonglong2 w1 = wb1;
            // lookahead: c=11 wraps to chunk 0 -> issued BEFORE the barrier,
            // keeps the LDS pipe busy across the exchange/finalize gap.
            const int nc = (c + 1 < CHUNKS_PER_G) ? c + 1 : 0;
            wb0 = wp0[(size_t)nc * HID];
            wb1 = wp1[(size_t)nc * HID];

            ulonglong2 ha = *reinterpret_cast<const ulonglong2*>(&myA[4 * c]);
            ulonglong2 hb = *reinterpret_cast<const ulonglong2*>(&myB[4 * c]);
            aA0 = fma2(w0.x, ha.x, aA0);  aA0 = fma2(w0.y, ha.y, aA0);
            aA1 = fma2(w1.x, ha.x, aA1);  aA1 = fma2(w1.y, ha.y, aA1);
            aB0 = fma2(w0.x, hb.x, aB0);  aB0 = fma2(w0.y, hb.y, aB0);
            aB1 = fma2(w1.x, hb.x, aB1);  aB1 = fma2(w1.y, hb.y, aB1);
        }
        #pragma unroll
        for (int i = 0; i < RF_U64 / 2; ++i) {
            ulonglong2 ha = *reinterpret_cast<const ulonglong2*>(&myA[SMEM_ROWS_G + 4 * i]);
            ulonglong2 hb = *reinterpret_cast<const ulonglong2*>(&myB[SMEM_ROWS_G + 4 * i]);
            aA0 = fma2(wr0[2 * i], ha.x, aA0);  aA0 = fma2(wr0[2 * i + 1], ha.y, aA0);
            aA1 = fma2(wr1[2 * i], ha.x, aA1);  aA1 = fma2(wr1[2 * i + 1], ha.y, aA1);
            aB0 = fma2(wr0[2 * i], hb.x, aB0);  aB0 = fma2(wr0[2 * i + 1], hb.y, aB0);
            aB1 = fma2(wr1[2 * i], hb.x, aB1);  aB1 = fma2(wr1[2 * i + 1], hb.y, aB1);
        }

        redp[(0 * NGROUP + g) * HID + j0] = sum2(aA0);
        redp[(0 * NGROUP + g) * HID + j1] = sum2(aA1);
        redp[(1 * NGROUP + g) * HID + j0] = sum2(aB0);
        redp[(1 * NGROUP + g) * HID + j1] = sum2(aB1);
        __syncthreads();                       // the ONE full-CTA barrier

        // ---- finalize own j-range ----
        if (act) {
            const float* rA = redp;
            const float* rB = redp + NGROUP * HID;
            const float sA = rA[0 * HID + myj] + rA[1 * HID + myj]
                           + rA[2 * HID + myj] + rA[3 * HID + myj];
            const float sB = rB[0 * HID + myj] + rB[1 * HID + myj]
                           + rB[2 * HID + myj] + rB[3 * HID + myj];
            const float hnA = fmaxf(myA[lidx] * 0.8f + (sA + nz) * 0.2f, 0.f);
            const float hnB = fmaxf(myB[lidx] * 0.8f + (sB + nz) * 0.2f, 0.f);
            if (out) {
                out[((size_t)t * BATCH + b0) * HID + myj] = hnA;
                out[((size_t)t * BATCH + b1) * HID + myj] = hnB;
            }
            myA[lidx] = hnA;
            myB[lidx] = hnB;
        }
        if (g == 0)
            (xb ? myB : myA)[xi] = xn;
        nz = nzn;

        asm volatile("bar.sync %0, %1;" :: "r"(g + 1), "r"(128) : "memory");
    }

    if (hlast && act) {
        hlast[b0 * HID + myj] = myA[lidx];
        hlast[b1 * HID + myj] = myB[lidx];
    }
}

extern "C" void kernel_launch(void* const* d_in, const int* in_sizes, int n_in,
                              void* d_out, int out_size)
{
    const float* x     = (const float*)d_in[0];   // [512,256,64]
    const float* h0    = (const float*)d_in[1];   // [256,256]
    const float* noise = (const float*)d_in[2];   // [512,256]
    const float* Win   = (const float*)d_in[3];   // [256,64]
    const float* bin   = (const float*)d_in[4];   // [256]
    const float* Whh   = (const float*)d_in[5];   // [256,256]
    const float* bhh   = (const float*)d_in[6];   // [256]

    const size_t TBH = (size_t)T_STEPS * BATCH * HID;
    const size_t BH  = (size_t)BATCH * HID;

    float* out   = nullptr;
    float* hlast = nullptr;
    if ((size_t)out_size >= TBH) {
        out = (float*)d_out;
        if ((size_t)out_size >= TBH + BH) hlast = (float*)d_out + TBH;
    } else {
        hlast = (float*)d_out;
    }

    static bool attr_set = false;
    if (!attr_set) {
        cudaFuncSetAttribute(ctrnn_wpipe_kernel,
                             cudaFuncAttributeMaxDynamicSharedMemorySize, SMEM_TOTAL);
        attr_set = true;
    }

    ctrnn_wpipe_kernel<<<NCTA, NTHR, SMEM_TOTAL>>>(
        x, h0, noise, Win, bin, Whh, bhh, out, hlast);
}